// round 7
// baseline (speedup 1.0000x reference)
#include <cuda_runtime.h>
#include <cuda_bf16.h>

#define N_NODES 20000
#define N_EDGES 5000
#define STEPS 50
#define EDGE_STRIDE 128     // max nodes per edge (mean ~40)
#define NODE_STRIDE 64      // max edges per node (mean ~10)

#define NBLK 148            // <= SM count -> all CTAs co-resident at occ 1
#define NTHR 512
#define NWARPS (NBLK * (NTHR / 32))
#define NTHREADS_TOT (NBLK * NTHR)
#define BATCH 8             // build-phase MLP batch (8 independent LDG.128)

// ---------------- scratch (device globals: no allocation allowed) ----------
__device__ int   g_edge_cnt[N_EDGES];
__device__ int   g_node_cnt[N_NODES];
__device__ int   g_edge_nodes[N_EDGES * EDGE_STRIDE];   // nodes in each edge
__device__ int   g_node_edges[N_NODES * NODE_STRIDE];   // edges touching each node
__device__ float g_agg[N_EDGES];                        // H @ I
__device__ float g_I[N_NODES];                          // current infected fraction

// grid barrier (arrive returns to 0 per barrier; gen monotonic -> replay-safe)
__device__ unsigned g_bar_arrive;
__device__ unsigned g_bar_gen;

// ---------------- software grid barrier (148 co-resident CTAs) --------------
__device__ __forceinline__ void gsync() {
    __syncthreads();
    if (threadIdx.x == 0) {
        __threadfence();
        unsigned gen = *(volatile unsigned*)&g_bar_gen;
        if (atomicAdd(&g_bar_arrive, 1u) == NBLK - 1) {
            g_bar_arrive = 0;
            __threadfence();
            *(volatile unsigned*)&g_bar_gen = gen + 1;
        } else {
            while (*(volatile unsigned*)&g_bar_gen == gen) { }
        }
        __threadfence();
    }
    __syncthreads();
}

// ---------------- the whole problem in ONE launch ---------------------------
__global__ void __launch_bounds__(NTHR, 1)
sir_all(const float*  __restrict__ x,
        const float4* __restrict__ H4,
        const float*  __restrict__ beta,
        const float*  __restrict__ gamma,
        float*        __restrict__ out) {
    const int tid  = threadIdx.x;
    const int gt   = blockIdx.x * NTHR + tid;
    const int lane = tid & 31;
    const int gw   = gt >> 5;

    // ---- phase 0: zero counters, traj[0] = x, seed g_I, load node regs ----
    for (int i = gt; i < N_EDGES; i += NTHREADS_TOT) g_edge_cnt[i] = 0;
    for (int i = gt; i < N_NODES; i += NTHREADS_TOT) g_node_cnt[i] = 0;

    const int n = gt;                   // owned node, one per thread
    float S = 0.f, I = 0.f, R = 0.f, bn = 0.f, gn = 0.f;
    if (n < N_NODES) {
        S  = x[n * 3 + 0];
        I  = x[n * 3 + 1];
        R  = x[n * 3 + 2];
        bn = beta[n];
        gn = gamma[n];
        out[n * 3 + 0] = S;
        out[n * 3 + 1] = I;
        out[n * 3 + 2] = R;
        g_I[n] = I;
    }
    gsync();

    // ---- phase 1: build sparse structure -- MLP-batched 400 MB scan -------
    // H row-major [N_EDGES][N_NODES], N_NODES % 4 == 0.
    // 8 independent LDG.128 issued back-to-back before any data-dependent
    // work => ~9.7 MB in flight grid-wide => bandwidth-bound, not latency.
    {
        const int row4   = N_NODES / 4;                 // 5000
        const int total4 = N_EDGES * row4;              // 25M
        for (int base = gt; base < total4; base += NTHREADS_TOT * BATCH) {
            float4 v[BATCH];
            #pragma unroll
            for (int k = 0; k < BATCH; k++) {
                int i = base + k * NTHREADS_TOT;
                v[k] = (i < total4) ? H4[i]
                                    : make_float4(0.f, 0.f, 0.f, 0.f);
            }
            #pragma unroll
            for (int k = 0; k < BATCH; k++) {
                if (v[k].x != 0.f || v[k].y != 0.f || v[k].z != 0.f || v[k].w != 0.f) {
                    int i  = base + k * NTHREADS_TOT;
                    int e  = i / row4;
                    int nb = (i - e * row4) * 4;
                    float vals[4] = {v[k].x, v[k].y, v[k].z, v[k].w};
                    #pragma unroll
                    for (int c = 0; c < 4; c++) {
                        if (vals[c] != 0.f) {
                            int nn = nb + c;
                            int p = atomicAdd(&g_edge_cnt[e], 1);
                            if (p < EDGE_STRIDE) g_edge_nodes[e * EDGE_STRIDE + p] = nn;
                            int q = atomicAdd(&g_node_cnt[nn], 1);
                            if (q < NODE_STRIDE) g_node_edges[nn * NODE_STRIDE + q] = e;
                        }
                    }
                }
            }
        }
    }
    gsync();

    // adjacency metadata for the owned node (immutable from here on)
    int ncnt = 0;
    if (n < N_NODES) {
        ncnt = __ldcg(&g_node_cnt[n]);
        ncnt = (ncnt < NODE_STRIDE) ? ncnt : NODE_STRIDE;
    }

    // ---- phase 2: 49 time steps ------------------------------------------
    for (int t = 1; t < STEPS; t++) {
        // A: agg[e] = sum_{node in e} I[node]   (warp per edge)
        for (int e = gw; e < N_EDGES; e += NWARPS) {
            int cnt = __ldcg(&g_edge_cnt[e]);
            cnt = (cnt < EDGE_STRIDE) ? cnt : EDGE_STRIDE;
            float s = 0.f;
            for (int j = lane; j < cnt; j += 32)
                s += __ldcg(&g_I[__ldcg(&g_edge_nodes[e * EDGE_STRIDE + j])]);
            #pragma unroll
            for (int o = 16; o; o >>= 1) s += __shfl_xor_sync(0xffffffffu, s, o);
            if (lane == 0) g_agg[e] = s;
        }
        gsync();

        // B: backward gather + SIR update (state held in registers)
        if (n < N_NODES) {
            float back = 0.f;
            #pragma unroll 4
            for (int j = 0; j < ncnt; j++)
                back += __ldcg(&g_agg[__ldcg(&g_node_edges[n * NODE_STRIDE + j])]);

            float nc = bn * S * back;     // new cases
            float nr = gn * I;            // new recoveries

            float s0 = fmaxf(S - nc,      0.f);
            float s1 = fmaxf(I + nc - nr, 0.f);
            float s2 = fmaxf(R + nr,      0.f);
            float inv = 1.f / (s0 + s1 + s2);
            S = s0 * inv; I = s1 * inv; R = s2 * inv;

            float* cur = out + (long)t * (N_NODES * 3) + n * 3;
            cur[0] = S; cur[1] = I; cur[2] = R;
            g_I[n] = I;
        }
        gsync();
    }
}

// ---------------- launcher --------------------------------------------------
extern "C" void kernel_launch(void* const* d_in, const int* in_sizes, int n_in,
                              void* d_out, int out_size) {
    const float*  x     = (const float*) d_in[0];
    const float4* H4    = (const float4*)d_in[1];
    const float*  beta  = (const float*) d_in[2];
    const float*  gamma = (const float*) d_in[3];
    float*        out   = (float*)d_out;

    sir_all<<<NBLK, NTHR>>>(x, H4, beta, gamma, out);
}

// round 8
// speedup vs baseline: 1.6316x; 1.6316x over previous
#include <cuda_runtime.h>
#include <cuda_bf16.h>

#define N_NODES 20000
#define N_EDGES 5000
#define STEPS 50
#define EDGE_STRIDE 128     // max nodes per edge (mean ~40)
#define NODE_STRIDE 64      // max edges per node (mean ~10)

#define NBLK 148            // <= SM count -> all CTAs co-resident at occ 1
#define NTHR 512
#define NWARPS (NBLK * (NTHR / 32))     // 2368
#define NTHREADS_TOT (NBLK * NTHR)

#define MAX_E_PER_WARP 3    // ceil(5000 / 2368)
#define POS_PER_LANE 4      // ceil(EDGE_STRIDE / 32)
#define NE_REG 24           // node->edge indices kept in registers

// ---------------- scratch (device globals: no allocation allowed) ----------
__device__ int   g_edge_cnt[N_EDGES];
__device__ int   g_node_cnt[N_NODES];
__device__ int   g_edge_nodes[N_EDGES * EDGE_STRIDE];
__device__ int   g_node_edges[N_NODES * NODE_STRIDE];
__device__ float g_agg[N_EDGES];        // H @ I  (mutable across barriers)
__device__ float g_I[N_NODES];          // infected fraction (mutable)

// grid barrier (arrive returns to 0 per barrier; gen monotonic -> replay-safe)
__device__ unsigned g_bar_arrive;
__device__ unsigned g_bar_gen;

// ---------------- init: zero counters, traj[0] = x, seed g_I ----------------
__global__ void k_init(const float* __restrict__ x, float* __restrict__ out) {
    int i = blockIdx.x * blockDim.x + threadIdx.x;
    if (i < N_EDGES) g_edge_cnt[i] = 0;
    if (i < N_NODES) {
        g_node_cnt[i] = 0;
        float s  = x[i * 3 + 0];
        float in = x[i * 3 + 1];
        float r  = x[i * 3 + 2];
        out[i * 3 + 0] = s;
        out[i * 3 + 1] = in;
        out[i * 3 + 2] = r;
        g_I[i] = in;
    }
}

// ---------------- build: big grid -> HBM-saturating scan --------------------
// H row-major [N_EDGES][N_NODES]; N_NODES % 4 == 0 so float4 stays in-row.
__global__ void k_build(const float4* __restrict__ H4) {
    const int row4   = N_NODES / 4;            // 5000 float4 per edge row
    const int total4 = N_EDGES * row4;         // 25M
    int stride = gridDim.x * blockDim.x;
    for (int i = blockIdx.x * blockDim.x + threadIdx.x; i < total4; i += stride) {
        float4 v = H4[i];
        if (v.x != 0.f || v.y != 0.f || v.z != 0.f || v.w != 0.f) {
            int e  = i / row4;
            int nb = (i - e * row4) * 4;
            float vals[4] = {v.x, v.y, v.z, v.w};
            #pragma unroll
            for (int k = 0; k < 4; k++) {
                if (vals[k] != 0.f) {
                    int nn = nb + k;
                    int p = atomicAdd(&g_edge_cnt[e], 1);
                    if (p < EDGE_STRIDE) g_edge_nodes[e * EDGE_STRIDE + p] = nn;
                    int q = atomicAdd(&g_node_cnt[nn], 1);
                    if (q < NODE_STRIDE) g_node_edges[nn * NODE_STRIDE + q] = e;
                }
            }
        }
    }
}

// ---------------- software grid barrier (148 co-resident CTAs) --------------
__device__ __forceinline__ void gsync() {
    __syncthreads();
    if (threadIdx.x == 0) {
        __threadfence();                       // release + (gpu scope) L1 inval
        unsigned gen = *(volatile unsigned*)&g_bar_gen;
        if (atomicAdd(&g_bar_arrive, 1u) == NBLK - 1) {
            g_bar_arrive = 0;
            __threadfence();
            *(volatile unsigned*)&g_bar_gen = gen + 1;
        } else {
            while (*(volatile unsigned*)&g_bar_gen == gen) { }
        }
        __threadfence();                       // acquire side
    }
    __syncthreads();
}

// ---------------- persistent step kernel: adjacency lives in registers ------
__global__ void __launch_bounds__(NTHR, 1)
sir_steps(const float* __restrict__ x,
          const float* __restrict__ beta,
          const float* __restrict__ gamma,
          float*       __restrict__ out) {
    const int tid  = threadIdx.x;
    const int gt   = blockIdx.x * NTHR + tid;
    const int lane = tid & 31;
    const int gw   = gt >> 5;

    // ---- hoist phase-A adjacency: this warp's edges -> per-lane registers --
    // Adjacency was written by k_build in a PREVIOUS launch: plain loads are
    // coherent and immutable for the whole kernel.
    int ecnt[MAX_E_PER_WARP];
    int eidx[MAX_E_PER_WARP][POS_PER_LANE];
    #pragma unroll
    for (int m = 0; m < MAX_E_PER_WARP; m++) {
        int e = gw + m * NWARPS;
        int cnt = 0;
        if (e < N_EDGES) {
            cnt = g_edge_cnt[e];
            cnt = (cnt < EDGE_STRIDE) ? cnt : EDGE_STRIDE;
        }
        ecnt[m] = cnt;
        #pragma unroll
        for (int k = 0; k < POS_PER_LANE; k++) {
            int j = lane + 32 * k;
            eidx[m][k] = (e < N_EDGES && j < cnt)
                       ? g_edge_nodes[e * EDGE_STRIDE + j] : -1;
        }
    }

    // ---- hoist phase-B adjacency + node state -----------------------------
    const int n = gt;
    float S = 0.f, I = 0.f, R = 0.f, bn = 0.f, gn = 0.f;
    int   ncnt = 0;
    int   ereg[NE_REG];
    if (n < N_NODES) {
        S  = x[n * 3 + 0];
        I  = x[n * 3 + 1];
        R  = x[n * 3 + 2];
        bn = beta[n];
        gn = gamma[n];
        ncnt = g_node_cnt[n];
        ncnt = (ncnt < NODE_STRIDE) ? ncnt : NODE_STRIDE;
    }
    #pragma unroll
    for (int j = 0; j < NE_REG; j++)
        ereg[j] = (n < N_NODES && j < ncnt) ? g_node_edges[n * NODE_STRIDE + j] : -1;

    // ---- 49 time steps ----------------------------------------------------
    for (int t = 1; t < STEPS; t++) {
        // A: agg[e] = sum_{node in e} I[node]  (indices in registers)
        #pragma unroll
        for (int m = 0; m < MAX_E_PER_WARP; m++) {
            int e = gw + m * NWARPS;
            if (e < N_EDGES) {
                float s = 0.f;
                #pragma unroll
                for (int k = 0; k < POS_PER_LANE; k++) {
                    int id = eidx[m][k];
                    if (id >= 0) s += __ldcg(&g_I[id]);
                }
                #pragma unroll
                for (int o = 16; o; o >>= 1) s += __shfl_xor_sync(0xffffffffu, s, o);
                if (lane == 0) g_agg[e] = s;
            }
        }
        gsync();

        // B: backward gather (indices in registers) + SIR update
        if (n < N_NODES) {
            float back = 0.f;
            #pragma unroll
            for (int j = 0; j < NE_REG; j++) {
                int e = ereg[j];
                if (e >= 0) back += __ldcg(&g_agg[e]);
            }
            for (int j = NE_REG; j < ncnt; j++)      // rare tail (P ~ 5e-5)
                back += __ldcg(&g_agg[g_node_edges[n * NODE_STRIDE + j]]);

            float nc = bn * S * back;     // new cases
            float nr = gn * I;            // new recoveries

            float s0 = fmaxf(S - nc,      0.f);
            float s1 = fmaxf(I + nc - nr, 0.f);
            float s2 = fmaxf(R + nr,      0.f);
            float inv = 1.f / (s0 + s1 + s2);
            S = s0 * inv; I = s1 * inv; R = s2 * inv;

            float* cur = out + (long)t * (N_NODES * 3) + n * 3;
            cur[0] = S; cur[1] = I; cur[2] = R;
            g_I[n] = I;
        }
        gsync();
    }
}

// ---------------- launcher --------------------------------------------------
extern "C" void kernel_launch(void* const* d_in, const int* in_sizes, int n_in,
                              void* d_out, int out_size) {
    const float*  x     = (const float*) d_in[0];
    const float4* H4    = (const float4*)d_in[1];
    const float*  beta  = (const float*) d_in[2];
    const float*  gamma = (const float*) d_in[3];
    float*        out   = (float*)d_out;

    k_init  <<<(N_NODES + 255) / 256, 256>>>(x, out);
    k_build <<<4096, 256>>>(H4);
    sir_steps<<<NBLK, NTHR>>>(x, beta, gamma, out);
}

// round 9
// speedup vs baseline: 1.8370x; 1.1259x over previous
#include <cuda_runtime.h>
#include <cuda_bf16.h>

#define N_NODES 20000
#define N_EDGES 5000
#define STEPS 50
#define EDGE_STRIDE 128     // max nodes per edge (mean ~40)
#define NODE_STRIDE 64      // max edges per node (mean ~10)

#define NBLK 148            // <= SM count -> all CTAs co-resident at occ 1
#define NTHR 512
#define NWARPS (NBLK * (NTHR / 32))     // 2368
#define NTHREADS_TOT (NBLK * NTHR)

#define MAX_E_PER_WARP 3    // ceil(5000 / 2368)
#define POS_PER_LANE 4      // ceil(EDGE_STRIDE / 32)
#define NE_REG 24           // node->edge indices kept in registers

// ---------------- scratch (device globals: no allocation allowed) ----------
__device__ int   g_edge_cnt[N_EDGES];
__device__ int   g_node_cnt[N_NODES];
__device__ int   g_edge_nodes[N_EDGES * EDGE_STRIDE];
__device__ int   g_node_edges[N_NODES * NODE_STRIDE];
__device__ float g_agg[N_EDGES];        // H @ I  (mutable across barriers)
__device__ float g_I[N_NODES];          // infected fraction (mutable)

// flag-based grid barrier state (all monotonic -> graph-replay safe, no reset)
__device__ unsigned g_flags[NBLK];      // per-CTA arrival flag (own line each)
__device__ unsigned g_gen;              // published generation

// ---------------- init: zero counters, traj[0] = x, seed g_I ----------------
__global__ void k_init(const float* __restrict__ x, float* __restrict__ out) {
    int i = blockIdx.x * blockDim.x + threadIdx.x;
    if (i < N_EDGES) g_edge_cnt[i] = 0;
    if (i < N_NODES) {
        g_node_cnt[i] = 0;
        float s  = x[i * 3 + 0];
        float in = x[i * 3 + 1];
        float r  = x[i * 3 + 2];
        out[i * 3 + 0] = s;
        out[i * 3 + 1] = in;
        out[i * 3 + 2] = r;
        g_I[i] = in;
    }
}

// ---------------- build: big grid -> HBM-saturating scan --------------------
// H row-major [N_EDGES][N_NODES]; N_NODES % 4 == 0 so float4 stays in-row.
__global__ void k_build(const float4* __restrict__ H4) {
    const int row4   = N_NODES / 4;            // 5000 float4 per edge row
    const int total4 = N_EDGES * row4;         // 25M
    int stride = gridDim.x * blockDim.x;
    for (int i = blockIdx.x * blockDim.x + threadIdx.x; i < total4; i += stride) {
        float4 v = H4[i];
        if (v.x != 0.f || v.y != 0.f || v.z != 0.f || v.w != 0.f) {
            int e  = i / row4;
            int nb = (i - e * row4) * 4;
            float vals[4] = {v.x, v.y, v.z, v.w};
            #pragma unroll
            for (int k = 0; k < 4; k++) {
                if (vals[k] != 0.f) {
                    int nn = nb + k;
                    int p = atomicAdd(&g_edge_cnt[e], 1);
                    if (p < EDGE_STRIDE) g_edge_nodes[e * EDGE_STRIDE + p] = nn;
                    int q = atomicAdd(&g_node_cnt[nn], 1);
                    if (q < NODE_STRIDE) g_node_edges[nn * NODE_STRIDE + q] = e;
                }
            }
        }
    }
}

// ---------------- flag-based grid barrier (parallel arrive/detect) ----------
// CTA leaders store barno into distinct flag slots (parallel). CTA 0 polls all
// 148 flags with 148 threads (one load latency), then publishes g_gen = barno.
__device__ __forceinline__ void gsync(unsigned barno) {
    __syncthreads();
    if (blockIdx.x == 0) {
        if (threadIdx.x == 0) {
            __threadfence();                               // release own stores
            *(volatile unsigned*)&g_flags[0] = barno;
        }
        if (threadIdx.x < NBLK) {                          // parallel detect
            while (*(volatile unsigned*)&g_flags[threadIdx.x] < barno) { }
        }
        __syncthreads();                                   // all flags seen
        if (threadIdx.x == 0) {
            __threadfence();
            *(volatile unsigned*)&g_gen = barno;           // publish
        }
    } else {
        if (threadIdx.x == 0) {
            __threadfence();                               // release own stores
            *(volatile unsigned*)&g_flags[blockIdx.x] = barno;
            while (*(volatile unsigned*)&g_gen < barno) { }
            __threadfence();                               // acquire
        }
    }
    __syncthreads();
}

// ---------------- persistent step kernel: adjacency lives in registers ------
__global__ void __launch_bounds__(NTHR, 1)
sir_steps(const float* __restrict__ x,
          const float* __restrict__ beta,
          const float* __restrict__ gamma,
          float*       __restrict__ out) {
    const int tid  = threadIdx.x;
    const int gt   = blockIdx.x * NTHR + tid;
    const int lane = tid & 31;
    const int gw   = gt >> 5;

    // barrier base: monotonic across graph replays (read once, CTA-uniform)
    __shared__ unsigned s_base;
    if (tid == 0) s_base = *(volatile unsigned*)&g_gen;
    __syncthreads();
    unsigned barno = s_base + 1;

    // ---- hoist phase-A adjacency: this warp's edges -> per-lane registers --
    // Written by k_build in a PREVIOUS launch: plain loads, immutable here.
    int eidx[MAX_E_PER_WARP][POS_PER_LANE];
    #pragma unroll
    for (int m = 0; m < MAX_E_PER_WARP; m++) {
        int e = gw + m * NWARPS;
        int cnt = 0;
        if (e < N_EDGES) {
            cnt = g_edge_cnt[e];
            cnt = (cnt < EDGE_STRIDE) ? cnt : EDGE_STRIDE;
        }
        #pragma unroll
        for (int k = 0; k < POS_PER_LANE; k++) {
            int j = lane + 32 * k;
            eidx[m][k] = (e < N_EDGES && j < cnt)
                       ? g_edge_nodes[e * EDGE_STRIDE + j] : -1;
        }
    }

    // ---- hoist phase-B adjacency + node state -----------------------------
    const int n = gt;
    float S = 0.f, I = 0.f, R = 0.f, bn = 0.f, gn = 0.f;
    int   ncnt = 0;
    int   ereg[NE_REG];
    if (n < N_NODES) {
        S  = x[n * 3 + 0];
        I  = x[n * 3 + 1];
        R  = x[n * 3 + 2];
        bn = beta[n];
        gn = gamma[n];
        ncnt = g_node_cnt[n];
        ncnt = (ncnt < NODE_STRIDE) ? ncnt : NODE_STRIDE;
    }
    #pragma unroll
    for (int j = 0; j < NE_REG; j++)
        ereg[j] = (n < N_NODES && j < ncnt) ? g_node_edges[n * NODE_STRIDE + j] : -1;

    // ---- 49 time steps ----------------------------------------------------
    for (int t = 1; t < STEPS; t++) {
        // A: agg[e] = sum_{node in e} I[node]  (indices in registers)
        #pragma unroll
        for (int m = 0; m < MAX_E_PER_WARP; m++) {
            int e = gw + m * NWARPS;
            if (e < N_EDGES) {
                float s = 0.f;
                #pragma unroll
                for (int k = 0; k < POS_PER_LANE; k++) {
                    int id = eidx[m][k];
                    if (id >= 0) s += __ldcg(&g_I[id]);
                }
                #pragma unroll
                for (int o = 16; o; o >>= 1) s += __shfl_xor_sync(0xffffffffu, s, o);
                if (lane == 0) g_agg[e] = s;
            }
        }
        gsync(barno); barno++;

        // B: backward gather (indices in registers) + SIR update
        if (n < N_NODES) {
            float back = 0.f;
            #pragma unroll
            for (int j = 0; j < NE_REG; j++) {
                int e = ereg[j];
                if (e >= 0) back += __ldcg(&g_agg[e]);
            }
            for (int j = NE_REG; j < ncnt; j++)      // rare tail (P ~ 5e-5)
                back += __ldcg(&g_agg[g_node_edges[n * NODE_STRIDE + j]]);

            float nc = bn * S * back;     // new cases
            float nr = gn * I;            // new recoveries

            float s0 = fmaxf(S - nc,      0.f);
            float s1 = fmaxf(I + nc - nr, 0.f);
            float s2 = fmaxf(R + nr,      0.f);
            float inv = 1.f / (s0 + s1 + s2);
            S = s0 * inv; I = s1 * inv; R = s2 * inv;

            float* cur = out + (long)t * (N_NODES * 3) + n * 3;
            cur[0] = S; cur[1] = I; cur[2] = R;
            g_I[n] = I;
        }
        if (t < STEPS - 1) {              // last step needs no trailing barrier
            gsync(barno); barno++;
        }
    }
}

// ---------------- launcher --------------------------------------------------
extern "C" void kernel_launch(void* const* d_in, const int* in_sizes, int n_in,
                              void* d_out, int out_size) {
    const float*  x     = (const float*) d_in[0];
    const float4* H4    = (const float4*)d_in[1];
    const float*  beta  = (const float*) d_in[2];
    const float*  gamma = (const float*) d_in[3];
    float*        out   = (float*)d_out;

    k_init  <<<(N_NODES + 255) / 256, 256>>>(x, out);
    k_build <<<4096, 256>>>(H4);
    sir_steps<<<NBLK, NTHR>>>(x, beta, gamma, out);
}